// round 15
// baseline (speedup 1.0000x reference)
#include <cuda_runtime.h>
#include <cuda_bf16.h>
#include <cstdint>

// Problem constants (fixed shapes from the reference setup)
#define NHEAD 8
#define CCH   16          // 2*NHEAD channels into the coverage conv
#define DCH   32          // conv output channels
#define BB    8           // batch
#define TT    256         // time steps
#define HH    16
#define WW    32
#define LL    512         // HH*WW
#define BTN   2048        // BB*TT
#define EPSV  1e-5f

#define KDENSE 400        // 16 ch * 25 taps, densely packed
#define NKS    25         // 400 / 16 k-steps

// ---------------- scratch (device globals; no allocations) ----------------
__device__ float g_gate[BB * CCH * TT];          // [b][c][t]
__device__ float g_cum [BTN * CCH * LL];         // [bt][c][l]  exclusive coverage
__device__ float g_cov [BTN * NHEAD * LL];       // [bt][n][l]  pre-BN projected cov
__device__ float g_stats[17];                    // [0..7]=sum, [8..15]=sumsq, [16]=cnt
__device__ unsigned char g_mask[BB * LL];        // canonical uint8 mask (1 = padded)
// B fragments, dense K: entry (ks*4+nf)*32+lane = uint4(Bh0, Bh1, Bl0, Bl1)
__device__ uint4 g_wfrag4[NKS * 4 * 32];

// =====================================================================
// helpers
// =====================================================================
__device__ __forceinline__ uint32_t bf16_split_pack(float x) {
    __nv_bfloat16 h = __float2bfloat16(x);
    __nv_bfloat16 lo = __float2bfloat16(x - __bfloat162float(h));
    return (uint32_t)__bfloat16_as_ushort(h) |
           ((uint32_t)__bfloat16_as_ushort(lo) << 16);
}

// D += A * B  (m16n8k16, row.col, bf16 in, f32 accum)
__device__ __forceinline__ void mma16816(float* d, const uint32_t* a,
                                         uint32_t b0, uint32_t b1) {
    asm volatile(
        "mma.sync.aligned.m16n8k16.row.col.f32.bf16.bf16.f32 "
        "{%0,%1,%2,%3}, {%4,%5,%6,%7}, {%8,%9}, {%0,%1,%2,%3};"
        : "+f"(d[0]), "+f"(d[1]), "+f"(d[2]), "+f"(d[3])
        : "r"(a[0]), "r"(a[1]), "r"(a[2]), "r"(a[3]), "r"(b0), "r"(b1));
}

// ======================================================================
// Kernel 0: canonicalize the key_padding_mask regardless of storage dtype.
// ======================================================================
__global__ void mask_prep_kernel(const unsigned char* __restrict__ m)
{
    __shared__ int c0, c1, c23;
    const int tid = threadIdx.x;  // 1024 threads
    if (tid == 0) { c0 = 0; c1 = 0; c23 = 0; }
    __syncthreads();
    int l0 = 0, l1 = 0, l23 = 0;
    for (int j = tid; j < BB * LL; j += 1024) {
        unsigned char v = m[j];
        if (v) {
            int r = j & 3;
            if (r == 0) l0++; else if (r == 1) l1++; else l23++;
        }
    }
    if (l0)  atomicAdd(&c0, l0);
    if (l1)  atomicAdd(&c1, l1);
    if (l23) atomicAdd(&c23, l23);
    __syncthreads();
    int dt;  // 0 = uint8, 1 = int32, 2 = float32
    if (c1 == 0 && c23 == 0)      dt = 1;
    else if (c0 == 0)             dt = 2;
    else                          dt = 0;
    for (int j = tid; j < BB * LL; j += 1024) {
        unsigned char r;
        if (dt == 1)      r = (((const int*)m)[j] != 0);
        else if (dt == 2) r = (((const float*)m)[j] != 0.f);
        else              r = (m[j] != 0);
        g_mask[j] = r;
    }
}

// ======================================================================
// Kernel 0b: build split-bf16 B fragments, dense-K layout.
// kg = c*25 + kk in [0,400).  Entry (ks*4+nf)*32+lane:
//   n = nf*8 + (lane>>2); kg0 = ks*16 + (lane&3)*2
//   pairs: rg0 = (kg0, kg0+1), rg1 = (kg0+8, kg0+9)
//   uint4 = (Bh_rg0, Bh_rg1, Bl_rg0, Bl_rg1)
// ======================================================================
__global__ void weights_prep_kernel(const float* __restrict__ convw)
{
    int i = blockIdx.x * 256 + threadIdx.x;   // 3200 entries
    if (i >= NKS * 4 * 32) return;
    const int lane = i & 31;
    const int nf   = (i >> 5) & 3;
    const int ks   = i >> 7;
    const int n  = (nf << 3) + (lane >> 2);
    const int kg0 = (ks << 4) + ((lane & 3) << 1);
    uint32_t ph[4], pl[4];
#pragma unroll
    for (int e = 0; e < 4; e++) {
        int kg = kg0 + ((e >> 1) << 3) + (e & 1);   // kg0, kg0+1, kg0+8, kg0+9
        int c = kg / 25, kk = kg - c * 25;
        float w = convw[(n * 16 + c) * 25 + kk];
        uint32_t p = bf16_split_pack(w);
        ph[e] = p; pl[e] = p;
    }
    uint4 r;
    r.x = __byte_perm(ph[0], ph[1], 0x5410);   // Bh rg0
    r.y = __byte_perm(ph[2], ph[3], 0x5410);   // Bh rg1
    r.z = __byte_perm(pl[0], pl[1], 0x7632);   // Bl rg0
    r.w = __byte_perm(pl[2], pl[3], 0x7632);   // Bl rg1
    g_wfrag4[i] = r;
}

// ======================================================================
// Kernel 1: gating network.  One CTA per (b,t) image.  (unchanged)
// ======================================================================
__global__ __launch_bounds__(128) void gate_kernel(
    const float* __restrict__ prev, const float* __restrict__ curr,
    const float* __restrict__ gw1, const float* __restrict__ gb1,
    const float* __restrict__ gw2, const float* __restrict__ gb2)
{
    __shared__ float att[CCH * LL];
    __shared__ float wsm[CCH * 9 * 8];
    __shared__ float red[4][8];
    __shared__ float pooled[8];

    const int bt = blockIdx.x;
    const int b  = bt >> 8;
    const int t  = bt & 255;
    const int tid = threadIdx.x;

#pragma unroll
    for (int k = 0; k < 16; k++) {
        int i = tid + k * 128;
        int c = i >> 7, j = i & 127;
        const float* src = (c < 8)
            ? prev + ((b * 8 + c) * TT + t) * LL
            : curr + ((b * 8 + (c - 8)) * TT + t) * LL;
        ((float4*)att)[i] = ((const float4*)src)[j];
    }
    for (int i = tid; i < 1152; i += 128) {
        int o = i / 144, ck = i - o * 144;
        wsm[ck * 8 + o] = gw1[i];
    }
    __syncthreads();

    const int row = tid >> 3;
    const int cb  = (tid & 7) * 4;

    float acc[8][4];
#pragma unroll
    for (int o = 0; o < 8; o++)
#pragma unroll
        for (int p = 0; p < 4; p++) acc[o][p] = 0.f;

    for (int c = 0; c < 16; c++) {
#pragma unroll
        for (int ky = 0; ky < 3; ky++) {
            int r = row + ky - 1;
            if ((unsigned)r >= 16u) continue;
            const float* ar = att + c * 512 + r * 32;
            float x[6];
            x[0] = (cb > 0)  ? ar[cb - 1] : 0.f;
            x[1] = ar[cb + 0];
            x[2] = ar[cb + 1];
            x[3] = ar[cb + 2];
            x[4] = ar[cb + 3];
            x[5] = (cb < 28) ? ar[cb + 4] : 0.f;
#pragma unroll
            for (int kx = 0; kx < 3; kx++) {
                const float4* wv = (const float4*)&wsm[(c * 9 + ky * 3 + kx) * 8];
                float4 wA = wv[0], wBv = wv[1];
                float w[8] = {wA.x, wA.y, wA.z, wA.w, wBv.x, wBv.y, wBv.z, wBv.w};
#pragma unroll
                for (int p = 0; p < 4; p++) {
                    float xv = x[kx + p];
#pragma unroll
                    for (int o = 0; o < 8; o++) acc[o][p] = fmaf(w[o], xv, acc[o][p]);
                }
            }
        }
    }

    float rs[8];
#pragma unroll
    for (int o = 0; o < 8; o++) {
        float bo = __ldg(gb1 + o);
        float s = 0.f;
#pragma unroll
        for (int p = 0; p < 4; p++) s += fmaxf(acc[o][p] + bo, 0.f);
        rs[o] = s;
    }
#pragma unroll
    for (int off = 16; off >= 1; off >>= 1)
#pragma unroll
        for (int o = 0; o < 8; o++) rs[o] += __shfl_xor_sync(0xffffffffu, rs[o], off);
    if ((tid & 31) == 0) {
#pragma unroll
        for (int o = 0; o < 8; o++) red[tid >> 5][o] = rs[o];
    }
    __syncthreads();
    if (tid < 8)
        pooled[tid] = (red[0][tid] + red[1][tid] + red[2][tid] + red[3][tid]) * (1.f / 512.f);
    __syncthreads();
    if (tid < 16) {
        float s = __ldg(gb2 + tid);
#pragma unroll
        for (int i = 0; i < 8; i++) s = fmaf(__ldg(gw2 + tid * 8 + i), pooled[i], s);
        g_gate[(b * 16 + tid) * TT + t] = 1.f / (1.f + expf(-s));
    }
}

// ======================================================================
// Kernel 2: gated exclusive cumsum over t.  256 CTAs x 256 threads:
// CTA = (b, c, l-half).  Unroll 8 for deeper MLP.
// ======================================================================
__global__ __launch_bounds__(256) void cumsum_kernel(
    const float* __restrict__ prev, const float* __restrict__ curr)
{
    __shared__ float gsh[TT];
    const int bid = blockIdx.x;
    const int bc = bid >> 1;
    const int b = bc >> 4, c = bc & 15;
    const int l = ((bid & 1) << 8) + threadIdx.x;
    gsh[threadIdx.x] = g_gate[bc * TT + threadIdx.x];
    __syncthreads();

    const float* src = ((c < 8) ? prev + (b * 8 + c) * TT * LL
                                : curr + (b * 8 + (c - 8)) * TT * LL) + l;
    float* dst = g_cum + (b * TT * CCH + c) * LL + l;

    float run = 0.f;
#pragma unroll 1
    for (int t = 0; t < TT; t += 8) {
        float a[8];
#pragma unroll
        for (int q = 0; q < 8; q++) a[q] = src[(t + q) * LL];
#pragma unroll
        for (int q = 0; q < 8; q++) {
            dst[(t + q) * (CCH * LL)] = run;
            run = fmaf(gsh[t + q], a[q], run);
        }
    }
}

// ======================================================================
// Kernel 3: zero the BN stat accumulators (must run each replay)
// ======================================================================
__global__ void init_stats_kernel()
{
    if (threadIdx.x < 17) g_stats[threadIdx.x] = 0.f;
}

// ======================================================================
// Kernel 4: implicit-GEMM conv5x5 via mma.sync (split-bf16, dense K=400)
//           + bias + relu + mask + 1x1 proj + BN stats.
// One CTA per (b,t) image, 256 threads = 8 warps; warp w owns px [w*64,(w+1)*64).
// 25 k-steps of 16; kg = c*25 + kk (no padding, no guards).
// SMEM (104608 B total -> 2 CTAs/SM):
//   0       img_sm u32 [16][20][40] packed (hi,lo) bf16 (51200 B)
//           (aliased post-mainloop by eo float[128][34] = 17408 B)
//   51200   bf4_sm uint4[3200] B-fragments                (51200 B)
//   102400  prj 1024 | 103424 cbs 128 | 103552 red 544 | 104096 msk 512
// ======================================================================
#define SM_BF_OFF   51200
#define SM_MISC     102400
#define CONV_SMEM_TOTAL 104608

__global__ __launch_bounds__(256, 2) void conv_mma_kernel(
    const float* __restrict__ convb, const float* __restrict__ projw)
{
    extern __shared__ char smc[];
    uint32_t* img_sm = (uint32_t*)smc;                   // [16][20][40]
    const uint4* bf4_sm = (const uint4*)(smc + SM_BF_OFF);
    float* prjf = (float*)(smc + SM_MISC);
    float* cbsf = (float*)(smc + SM_MISC + 1024);
    float* redf = (float*)(smc + SM_MISC + 1152);
    unsigned char* mskb = (unsigned char*)(smc + SM_MISC + 1696);

    const int bt = blockIdx.x;
    const int b  = bt >> 8;
    const int tid = threadIdx.x;
    const int wid = tid >> 5;
    const int lane = tid & 31;
    const int gr = lane >> 2;           // fragment row group (0..7)
    const int gc = (lane & 3) << 1;     // fragment k/col offset (0,2,4,6)

    // ---- load phase ----
#pragma unroll
    for (int i = tid; i < 3200; i += 256)
        ((uint4*)img_sm)[i] = make_uint4(0u, 0u, 0u, 0u);
#pragma unroll
    for (int i = tid; i < 3200; i += 256)
        ((uint4*)(smc + SM_BF_OFF))[i] = g_wfrag4[i];
    prjf[tid] = __ldg(projw + tid);
    if (tid < 32)  cbsf[tid] = __ldg(convb + tid);
    if (tid < 128) ((uint32_t*)mskb)[tid] = ((const uint32_t*)(g_mask + b * 512))[tid];
    __syncthreads();

    // interior: split-bf16 packed values
    const float* img = g_cum + bt * (CCH * LL);
#pragma unroll
    for (int i = tid; i < 8192; i += 256) {
        int c = i >> 9, rem = i & 511, r = rem >> 5, j = rem & 31;
        img_sm[(c * 20 + r + 2) * 40 + (j + 2)] = bf16_split_pack(img[i]);
    }
    __syncthreads();

    // pixel base offsets (p1 = p0 + 8 never crosses a 32-col row)
    int pb[4];
#pragma unroll
    for (int mf = 0; mf < 4; mf++) {
        int p0 = (wid << 6) + (mf << 4) + gr;
        pb[mf] = (p0 >> 5) * 40 + (p0 & 31);
    }

    // ---- main GEMM loop: 25 dense k-steps ----
    float acc[4][4][4];
#pragma unroll
    for (int mf = 0; mf < 4; mf++)
#pragma unroll
        for (int nf = 0; nf < 4; nf++)
#pragma unroll
            for (int j = 0; j < 4; j++) acc[mf][nf][j] = 0.f;

#pragma unroll 1
    for (int ks = 0; ks < NKS; ks++) {
        uint4 Bf[4];
#pragma unroll
        for (int nf = 0; nf < 4; nf++)
            Bf[nf] = bf4_sm[(ks * 4 + nf) * 32 + lane];

        const int kg0 = (ks << 4) + gc;
        int off[4];
#pragma unroll
        for (int j = 0; j < 4; j++) {
            int kg = kg0 + ((j & 2) << 2) + (j & 1);   // kg0, +1, +8, +9
            int c = kg / 25, kk = kg - c * 25;
            int ky = kk / 5, kx = kk - ky * 5;
            off[j] = c * 800 + ky * 40 + kx;
        }

#pragma unroll
        for (int mf = 0; mf < 4; mf++) {
            const int b0 = pb[mf];
            const int b1 = b0 + 8;
            uint32_t v0 = img_sm[b0 + off[0]];
            uint32_t v1 = img_sm[b0 + off[1]];
            uint32_t v2 = img_sm[b1 + off[0]];
            uint32_t v3 = img_sm[b1 + off[1]];
            uint32_t v4 = img_sm[b0 + off[2]];
            uint32_t v5 = img_sm[b0 + off[3]];
            uint32_t v6 = img_sm[b1 + off[2]];
            uint32_t v7 = img_sm[b1 + off[3]];
            uint32_t Ah[4], Al[4];
            Ah[0] = __byte_perm(v0, v1, 0x5410); Al[0] = __byte_perm(v0, v1, 0x7632);
            Ah[1] = __byte_perm(v2, v3, 0x5410); Al[1] = __byte_perm(v2, v3, 0x7632);
            Ah[2] = __byte_perm(v4, v5, 0x5410); Al[2] = __byte_perm(v4, v5, 0x7632);
            Ah[3] = __byte_perm(v6, v7, 0x5410); Al[3] = __byte_perm(v6, v7, 0x7632);
#pragma unroll
            for (int nf = 0; nf < 4; nf++) {
                mma16816(acc[mf][nf], Ah, Bf[nf].x, Bf[nf].y);
                mma16816(acc[mf][nf], Ah, Bf[nf].z, Bf[nf].w);
                mma16816(acc[mf][nf], Al, Bf[nf].x, Bf[nf].y);
            }
        }
    }

    // ---- per-mf epilogue (eo aliases dead img region) ----
    float* eo = (float*)smc;   // [128][34]
    float lsum[4] = {0,0,0,0}, lsq[4] = {0,0,0,0};
    float lcnt = 0.f;
    const int hh = (tid & 1) << 2;

#pragma unroll 1
    for (int mf = 0; mf < 4; mf++) {
        __syncthreads();
        const int row0 = (wid << 4) + gr;
        const int row1 = row0 + 8;
#pragma unroll
        for (int nf = 0; nf < 4; nf++) {
            const int n0 = (nf << 3) + gc;
            float bA = cbsf[n0], bBv = cbsf[n0 + 1];
            eo[row0 * 34 + n0]     = fmaxf(acc[mf][nf][0] + bA,  0.f);
            eo[row0 * 34 + n0 + 1] = fmaxf(acc[mf][nf][1] + bBv, 0.f);
            eo[row1 * 34 + n0]     = fmaxf(acc[mf][nf][2] + bA,  0.f);
            eo[row1 * 34 + n0 + 1] = fmaxf(acc[mf][nf][3] + bBv, 0.f);
        }
        __syncthreads();

        const int lr = tid >> 1;
        const int px = ((lr >> 4) << 6) + (mf << 4) + (lr & 15);
        float f[32];
#pragma unroll
        for (int q = 0; q < 16; q++) {
            float2 t2 = *(float2*)&eo[lr * 34 + (q << 1)];
            f[2 * q] = t2.x; f[2 * q + 1] = t2.y;
        }
        const bool pm = (mskb[px] != 0);
        if (hh == 0 && !pm) lcnt += 1.f;
        float* outp = g_cov + bt * (NHEAD * LL) + px;
#pragma unroll
        for (int hq = 0; hq < 4; hq++) {
            const int h = hh + hq;
            float s = 0.f;
            const float4* pv = (const float4*)(prjf + h * 32);
#pragma unroll
            for (int og = 0; og < 8; og++) {
                float4 p4 = pv[og];
                s = fmaf(p4.x, f[og * 4 + 0], s);
                s = fmaf(p4.y, f[og * 4 + 1], s);
                s = fmaf(p4.z, f[og * 4 + 2], s);
                s = fmaf(p4.w, f[og * 4 + 3], s);
            }
            if (pm) s = 0.f;
            outp[h * LL] = s;
            lsum[hq] += s;
            lsq[hq]  += s * s;
        }
    }

    // stats reduce: even lanes hold heads 0-3, odd lanes heads 4-7
#pragma unroll
    for (int off = 2; off <= 16; off <<= 1) {
#pragma unroll
        for (int hq = 0; hq < 4; hq++) {
            lsum[hq] += __shfl_xor_sync(0xffffffffu, lsum[hq], off);
            lsq[hq]  += __shfl_xor_sync(0xffffffffu, lsq[hq],  off);
        }
        lcnt += __shfl_xor_sync(0xffffffffu, lcnt, off);
    }
    if (lane == 0) {
        float* rr = redf + wid * 17;
#pragma unroll
        for (int hq = 0; hq < 4; hq++) { rr[hq] = lsum[hq]; rr[8 + hq] = lsq[hq]; }
        rr[16] = lcnt;
    }
    if (lane == 1) {
        float* rr = redf + wid * 17;
#pragma unroll
        for (int hq = 0; hq < 4; hq++) { rr[4 + hq] = lsum[hq]; rr[12 + hq] = lsq[hq]; }
    }
    __syncthreads();
    if (tid < 17) {
        float s = 0.f;
#pragma unroll
        for (int w = 0; w < 8; w++) s += redf[w * 17 + tid];
        atomicAdd(&g_stats[tid], s);
    }
}

// ======================================================================
// Kernel 5: masked batch-norm + transpose to [b*n][t][l] output layout
// ======================================================================
__global__ __launch_bounds__(256) void final_kernel(
    const float* __restrict__ gamma, const float* __restrict__ beta,
    float* __restrict__ out)
{
    int vid = blockIdx.x * 256 + threadIdx.x;   // float4 id
    int f = vid << 2;
    int b  = f >> 20;
    int nh = (f >> 17) & 7;
    int t  = (f >> 9) & 255;
    int l  = f & 511;

    float cnt  = g_stats[16];
    float mean = g_stats[nh] / cnt;
    float var  = g_stats[8 + nh] / cnt - mean * mean;
    float sc = rsqrtf(var + EPSV) * __ldg(gamma + nh);
    float sh = __ldg(beta + nh) - mean * sc;

    float4 v = *(const float4*)(g_cov + ((((b << 8) + t) * 8 + nh) << 9) + l);
    const unsigned char* mp = g_mask + (b << 9) + l;
    float4 r;
    r.x = mp[0] ? 0.f : fmaf(v.x, sc, sh);
    r.y = mp[1] ? 0.f : fmaf(v.y, sc, sh);
    r.z = mp[2] ? 0.f : fmaf(v.z, sc, sh);
    r.w = mp[3] ? 0.f : fmaf(v.w, sc, sh);
    ((float4*)out)[vid] = r;
}

// ======================================================================
// Launch
// ======================================================================
extern "C" void kernel_launch(void* const* d_in, const int* in_sizes, int n_in,
                              void* d_out, int out_size)
{
    (void)in_sizes; (void)out_size;
    const bool has_scalars = (n_in >= 14);
    const float*         prev  = (const float*)d_in[0];
    const unsigned char* mask  = (const unsigned char*)d_in[1];
    const float*         curr  = (const float*)d_in[has_scalars ? 3 : 2];
    const int            base  = has_scalars ? 5 : 3;
    const float*         convw = (const float*)d_in[base + 0];
    const float*         convb = (const float*)d_in[base + 1];
    const float*         projw = (const float*)d_in[base + 2];
    const float*         gw1   = (const float*)d_in[base + 3];
    const float*         gb1   = (const float*)d_in[base + 4];
    const float*         gw2   = (const float*)d_in[base + 5];
    const float*         gb2   = (const float*)d_in[base + 6];
    const float*         gamma = (const float*)d_in[base + 7];
    const float*         beta  = (const float*)d_in[base + 8];

    cudaFuncSetAttribute(conv_mma_kernel,
                         cudaFuncAttributeMaxDynamicSharedMemorySize,
                         CONV_SMEM_TOTAL);

    mask_prep_kernel<<<1, 1024>>>(mask);
    weights_prep_kernel<<<13, 256>>>(convw);
    gate_kernel<<<BTN, 128>>>(prev, curr, gw1, gb1, gw2, gb2);
    cumsum_kernel<<<BB * CCH * 2, 256>>>(prev, curr);
    init_stats_kernel<<<1, 32>>>();
    conv_mma_kernel<<<BTN, 256, CONV_SMEM_TOTAL>>>(convb, projw);
    final_kernel<<<8192, 256>>>(gamma, beta, (float*)d_out);
}

// round 16
// speedup vs baseline: 1.5585x; 1.5585x over previous
#include <cuda_runtime.h>
#include <cuda_bf16.h>
#include <cstdint>

// Problem constants (fixed shapes from the reference setup)
#define NHEAD 8
#define CCH   16          // 2*NHEAD channels into the coverage conv
#define DCH   32          // conv output channels
#define BB    8           // batch
#define TT    256         // time steps
#define HH    16
#define WW    32
#define LL    512         // HH*WW
#define BTN   2048        // BB*TT
#define EPSV  1e-5f

#define KDENSE 400        // 16 ch * 25 taps, densely packed
#define NKS    25         // 400 / 16 k-steps

// ---------------- scratch (device globals; no allocations) ----------------
__device__ float g_gate[BB * CCH * TT];          // [b][c][t]
__device__ float g_cum [BTN * CCH * LL];         // [bt][c][l]  exclusive coverage
__device__ float g_cov [BTN * NHEAD * LL];       // [bt][n][l]  pre-BN projected cov
__device__ float g_stats[17];                    // [0..7]=sum, [8..15]=sumsq, [16]=cnt
__device__ unsigned char g_mask[BB * LL];        // canonical uint8 mask (1 = padded)
// B fragments, dense K: entry (ks*4+nf)*32+lane = uint4(Bh0, Bh1, Bl0, Bl1)
__device__ uint4 g_wfrag4[NKS * 4 * 32];

// =====================================================================
// helpers
// =====================================================================
__device__ __forceinline__ uint32_t bf16_split_pack(float x) {
    __nv_bfloat16 h = __float2bfloat16(x);
    __nv_bfloat16 lo = __float2bfloat16(x - __bfloat162float(h));
    return (uint32_t)__bfloat16_as_ushort(h) |
           ((uint32_t)__bfloat16_as_ushort(lo) << 16);
}

// D += A * B  (m16n8k16, row.col, bf16 in, f32 accum)
__device__ __forceinline__ void mma16816(float* d, const uint32_t* a,
                                         uint32_t b0, uint32_t b1) {
    asm volatile(
        "mma.sync.aligned.m16n8k16.row.col.f32.bf16.bf16.f32 "
        "{%0,%1,%2,%3}, {%4,%5,%6,%7}, {%8,%9}, {%0,%1,%2,%3};"
        : "+f"(d[0]), "+f"(d[1]), "+f"(d[2]), "+f"(d[3])
        : "r"(a[0]), "r"(a[1]), "r"(a[2]), "r"(a[3]), "r"(b0), "r"(b1));
}

// ======================================================================
// Kernel 0: canonicalize the key_padding_mask regardless of storage dtype.
// ======================================================================
__global__ void mask_prep_kernel(const unsigned char* __restrict__ m)
{
    __shared__ int c0, c1, c23;
    const int tid = threadIdx.x;  // 1024 threads
    if (tid == 0) { c0 = 0; c1 = 0; c23 = 0; }
    __syncthreads();
    int l0 = 0, l1 = 0, l23 = 0;
    for (int j = tid; j < BB * LL; j += 1024) {
        unsigned char v = m[j];
        if (v) {
            int r = j & 3;
            if (r == 0) l0++; else if (r == 1) l1++; else l23++;
        }
    }
    if (l0)  atomicAdd(&c0, l0);
    if (l1)  atomicAdd(&c1, l1);
    if (l23) atomicAdd(&c23, l23);
    __syncthreads();
    int dt;  // 0 = uint8, 1 = int32, 2 = float32
    if (c1 == 0 && c23 == 0)      dt = 1;
    else if (c0 == 0)             dt = 2;
    else                          dt = 0;
    for (int j = tid; j < BB * LL; j += 1024) {
        unsigned char r;
        if (dt == 1)      r = (((const int*)m)[j] != 0);
        else if (dt == 2) r = (((const float*)m)[j] != 0.f);
        else              r = (m[j] != 0);
        g_mask[j] = r;
    }
}

// ======================================================================
// Kernel 0b: build split-bf16 B fragments, dense-K layout.
// kg = c*25 + kk in [0,400).  Entry (ks*4+nf)*32+lane:
//   n = nf*8 + (lane>>2); kg0 = ks*16 + (lane&3)*2
//   pairs: rg0 = (kg0, kg0+1), rg1 = (kg0+8, kg0+9)
//   uint4 = (Bh_rg0, Bh_rg1, Bl_rg0, Bl_rg1)
// ======================================================================
__global__ void weights_prep_kernel(const float* __restrict__ convw)
{
    int i = blockIdx.x * 256 + threadIdx.x;   // 3200 entries
    if (i >= NKS * 4 * 32) return;
    const int lane = i & 31;
    const int nf   = (i >> 5) & 3;
    const int ks   = i >> 7;
    const int n  = (nf << 3) + (lane >> 2);
    const int kg0 = (ks << 4) + ((lane & 3) << 1);
    uint32_t p[4];
#pragma unroll
    for (int e = 0; e < 4; e++) {
        int kg = kg0 + ((e >> 1) << 3) + (e & 1);   // kg0, kg0+1, kg0+8, kg0+9
        int c = kg / 25, kk = kg - c * 25;
        float w = convw[(n * 16 + c) * 25 + kk];
        p[e] = bf16_split_pack(w);
    }
    uint4 r;
    r.x = __byte_perm(p[0], p[1], 0x5410);   // Bh rg0
    r.y = __byte_perm(p[2], p[3], 0x5410);   // Bh rg1
    r.z = __byte_perm(p[0], p[1], 0x7632);   // Bl rg0
    r.w = __byte_perm(p[2], p[3], 0x7632);   // Bl rg1
    g_wfrag4[i] = r;
}

// ======================================================================
// Kernel 1: gating network.  One CTA per (b,t) image.  (unchanged)
// ======================================================================
__global__ __launch_bounds__(128) void gate_kernel(
    const float* __restrict__ prev, const float* __restrict__ curr,
    const float* __restrict__ gw1, const float* __restrict__ gb1,
    const float* __restrict__ gw2, const float* __restrict__ gb2)
{
    __shared__ float att[CCH * LL];
    __shared__ float wsm[CCH * 9 * 8];
    __shared__ float red[4][8];
    __shared__ float pooled[8];

    const int bt = blockIdx.x;
    const int b  = bt >> 8;
    const int t  = bt & 255;
    const int tid = threadIdx.x;

#pragma unroll
    for (int k = 0; k < 16; k++) {
        int i = tid + k * 128;
        int c = i >> 7, j = i & 127;
        const float* src = (c < 8)
            ? prev + ((b * 8 + c) * TT + t) * LL
            : curr + ((b * 8 + (c - 8)) * TT + t) * LL;
        ((float4*)att)[i] = ((const float4*)src)[j];
    }
    for (int i = tid; i < 1152; i += 128) {
        int o = i / 144, ck = i - o * 144;
        wsm[ck * 8 + o] = gw1[i];
    }
    __syncthreads();

    const int row = tid >> 3;
    const int cb  = (tid & 7) * 4;

    float acc[8][4];
#pragma unroll
    for (int o = 0; o < 8; o++)
#pragma unroll
        for (int p = 0; p < 4; p++) acc[o][p] = 0.f;

    for (int c = 0; c < 16; c++) {
#pragma unroll
        for (int ky = 0; ky < 3; ky++) {
            int r = row + ky - 1;
            if ((unsigned)r >= 16u) continue;
            const float* ar = att + c * 512 + r * 32;
            float x[6];
            x[0] = (cb > 0)  ? ar[cb - 1] : 0.f;
            x[1] = ar[cb + 0];
            x[2] = ar[cb + 1];
            x[3] = ar[cb + 2];
            x[4] = ar[cb + 3];
            x[5] = (cb < 28) ? ar[cb + 4] : 0.f;
#pragma unroll
            for (int kx = 0; kx < 3; kx++) {
                const float4* wv = (const float4*)&wsm[(c * 9 + ky * 3 + kx) * 8];
                float4 wA = wv[0], wBv = wv[1];
                float w[8] = {wA.x, wA.y, wA.z, wA.w, wBv.x, wBv.y, wBv.z, wBv.w};
#pragma unroll
                for (int p = 0; p < 4; p++) {
                    float xv = x[kx + p];
#pragma unroll
                    for (int o = 0; o < 8; o++) acc[o][p] = fmaf(w[o], xv, acc[o][p]);
                }
            }
        }
    }

    float rs[8];
#pragma unroll
    for (int o = 0; o < 8; o++) {
        float bo = __ldg(gb1 + o);
        float s = 0.f;
#pragma unroll
        for (int p = 0; p < 4; p++) s += fmaxf(acc[o][p] + bo, 0.f);
        rs[o] = s;
    }
#pragma unroll
    for (int off = 16; off >= 1; off >>= 1)
#pragma unroll
        for (int o = 0; o < 8; o++) rs[o] += __shfl_xor_sync(0xffffffffu, rs[o], off);
    if ((tid & 31) == 0) {
#pragma unroll
        for (int o = 0; o < 8; o++) red[tid >> 5][o] = rs[o];
    }
    __syncthreads();
    if (tid < 8)
        pooled[tid] = (red[0][tid] + red[1][tid] + red[2][tid] + red[3][tid]) * (1.f / 512.f);
    __syncthreads();
    if (tid < 16) {
        float s = __ldg(gb2 + tid);
#pragma unroll
        for (int i = 0; i < 8; i++) s = fmaf(__ldg(gw2 + tid * 8 + i), pooled[i], s);
        g_gate[(b * 16 + tid) * TT + t] = 1.f / (1.f + expf(-s));
    }
}

// ======================================================================
// Kernel 2: gated exclusive cumsum over t.  256 CTAs x 256 threads:
// CTA = (b, c, l-half).  Unroll 8 for deeper MLP.  (kept from R15: 31us)
// ======================================================================
__global__ __launch_bounds__(256) void cumsum_kernel(
    const float* __restrict__ prev, const float* __restrict__ curr)
{
    __shared__ float gsh[TT];
    const int bid = blockIdx.x;
    const int bc = bid >> 1;
    const int b = bc >> 4, c = bc & 15;
    const int l = ((bid & 1) << 8) + threadIdx.x;
    gsh[threadIdx.x] = g_gate[bc * TT + threadIdx.x];
    __syncthreads();

    const float* src = ((c < 8) ? prev + (b * 8 + c) * TT * LL
                                : curr + (b * 8 + (c - 8)) * TT * LL) + l;
    float* dst = g_cum + (b * TT * CCH + c) * LL + l;

    float run = 0.f;
#pragma unroll 1
    for (int t = 0; t < TT; t += 8) {
        float a[8];
#pragma unroll
        for (int q = 0; q < 8; q++) a[q] = src[(t + q) * LL];
#pragma unroll
        for (int q = 0; q < 8; q++) {
            dst[(t + q) * (CCH * LL)] = run;
            run = fmaf(gsh[t + q], a[q], run);
        }
    }
}

// ======================================================================
// Kernel 3: zero the BN stat accumulators (must run each replay)
// ======================================================================
__global__ void init_stats_kernel()
{
    if (threadIdx.x < 17) g_stats[threadIdx.x] = 0.f;
}

// ======================================================================
// Kernel 4: implicit-GEMM conv5x5 via mma.sync (split-bf16, dense K=400)
//           + bias + relu + mask + 1x1 proj + BN stats.
// One CTA per (b,t) image, 256 threads = 8 warps; warp w owns px [w*64,(w+1)*64).
// NO min-blocks cap: the 64-float accumulator set must stay in registers
// (R15 post-mortem: __launch_bounds__(256,2) spilled and cost +140us).
// SMEM (174240 B, 1 CTA/SM):
//   0       out_sm float [512][34]                        (69632 B)
//   69632   img_sm u32 [16][20][40] packed (hi,lo) bf16   (51200 B)
//   120832  bf4_sm uint4[3200] B-fragments                (51200 B)
//   172032  prj 1024 | 173056 cbs 128 | 173184 red 544 | 173728 msk 512
// ======================================================================
#define SM_IMG_OFF  69632
#define SM_BF_OFF   120832
#define SM_MISC     172032
#define CONV_SMEM_TOTAL 174240

__global__ __launch_bounds__(256) void conv_mma_kernel(
    const float* __restrict__ convb, const float* __restrict__ projw)
{
    extern __shared__ char smc[];
    float*    out_sm = (float*)smc;                      // [512][34]
    uint32_t* img_sm = (uint32_t*)(smc + SM_IMG_OFF);    // [16][20][40]
    const uint4* bf4_sm = (const uint4*)(smc + SM_BF_OFF);
    float* prjf = (float*)(smc + SM_MISC);
    float* cbsf = (float*)(smc + SM_MISC + 1024);
    float* redf = (float*)(smc + SM_MISC + 1152);
    unsigned char* mskb = (unsigned char*)(smc + SM_MISC + 1696);

    const int bt = blockIdx.x;
    const int b  = bt >> 8;
    const int tid = threadIdx.x;
    const int wid = tid >> 5;
    const int lane = tid & 31;
    const int gr = lane >> 2;           // fragment row group (0..7)
    const int gc = (lane & 3) << 1;     // fragment k/col offset (0,2,4,6)

    // ---- load phase ----
#pragma unroll
    for (int i = tid; i < 3200; i += 256)
        ((uint4*)img_sm)[i] = make_uint4(0u, 0u, 0u, 0u);
#pragma unroll
    for (int i = tid; i < 3200; i += 256)
        ((uint4*)(smc + SM_BF_OFF))[i] = g_wfrag4[i];
    prjf[tid] = __ldg(projw + tid);
    if (tid < 32)  cbsf[tid] = __ldg(convb + tid);
    if (tid < 128) ((uint32_t*)mskb)[tid] = ((const uint32_t*)(g_mask + b * 512))[tid];
    __syncthreads();

    // interior: split-bf16 packed values
    const float* img = g_cum + bt * (CCH * LL);
#pragma unroll
    for (int i = tid; i < 8192; i += 256) {
        int c = i >> 9, rem = i & 511, r = rem >> 5, j = rem & 31;
        img_sm[(c * 20 + r + 2) * 40 + (j + 2)] = bf16_split_pack(img[i]);
    }
    __syncthreads();

    // pixel base offsets (p1 = p0 + 8 never crosses a 32-col row)
    int pb[4];
#pragma unroll
    for (int mf = 0; mf < 4; mf++) {
        int p0 = (wid << 6) + (mf << 4) + gr;
        pb[mf] = (p0 >> 5) * 40 + (p0 & 31);
    }

    // ---- main GEMM loop: 25 dense k-steps ----
    float acc[4][4][4];
#pragma unroll
    for (int mf = 0; mf < 4; mf++)
#pragma unroll
        for (int nf = 0; nf < 4; nf++)
#pragma unroll
            for (int j = 0; j < 4; j++) acc[mf][nf][j] = 0.f;

#pragma unroll 1
    for (int ks = 0; ks < NKS; ks++) {
        uint4 Bf[4];
#pragma unroll
        for (int nf = 0; nf < 4; nf++)
            Bf[nf] = bf4_sm[(ks * 4 + nf) * 32 + lane];

        const int kg0 = (ks << 4) + gc;
        int off[4];
#pragma unroll
        for (int j = 0; j < 4; j++) {
            int kg = kg0 + ((j & 2) << 2) + (j & 1);   // kg0, +1, +8, +9
            int c = kg / 25, kk = kg - c * 25;
            int ky = kk / 5, kx = kk - ky * 5;
            off[j] = c * 800 + ky * 40 + kx;
        }

#pragma unroll
        for (int mf = 0; mf < 4; mf++) {
            const int b0 = pb[mf];
            const int b1 = b0 + 8;
            uint32_t v0 = img_sm[b0 + off[0]];
            uint32_t v1 = img_sm[b0 + off[1]];
            uint32_t v2 = img_sm[b1 + off[0]];
            uint32_t v3 = img_sm[b1 + off[1]];
            uint32_t v4 = img_sm[b0 + off[2]];
            uint32_t v5 = img_sm[b0 + off[3]];
            uint32_t v6 = img_sm[b1 + off[2]];
            uint32_t v7 = img_sm[b1 + off[3]];
            uint32_t Ah[4], Al[4];
            Ah[0] = __byte_perm(v0, v1, 0x5410); Al[0] = __byte_perm(v0, v1, 0x7632);
            Ah[1] = __byte_perm(v2, v3, 0x5410); Al[1] = __byte_perm(v2, v3, 0x7632);
            Ah[2] = __byte_perm(v4, v5, 0x5410); Al[2] = __byte_perm(v4, v5, 0x7632);
            Ah[3] = __byte_perm(v6, v7, 0x5410); Al[3] = __byte_perm(v6, v7, 0x7632);
#pragma unroll
            for (int nf = 0; nf < 4; nf++) {
                mma16816(acc[mf][nf], Ah, Bf[nf].x, Bf[nf].y);
                mma16816(acc[mf][nf], Ah, Bf[nf].z, Bf[nf].w);
                mma16816(acc[mf][nf], Al, Bf[nf].x, Bf[nf].y);
            }
        }
    }

    // ---- bias + relu, scatter to out_sm [px][34] ----
#pragma unroll
    for (int mf = 0; mf < 4; mf++) {
        const int p0 = (wid << 6) + (mf << 4) + gr;
        const int p1 = p0 + 8;
#pragma unroll
        for (int nf = 0; nf < 4; nf++) {
            const int n0 = (nf << 3) + gc;
            float bA = cbsf[n0], bBv = cbsf[n0 + 1];
            float2 w0, w1;
            w0.x = fmaxf(acc[mf][nf][0] + bA,  0.f);
            w0.y = fmaxf(acc[mf][nf][1] + bBv, 0.f);
            w1.x = fmaxf(acc[mf][nf][2] + bA,  0.f);
            w1.y = fmaxf(acc[mf][nf][3] + bBv, 0.f);
            *(float2*)&out_sm[p0 * 34 + n0] = w0;
            *(float2*)&out_sm[p1 * 34 + n0] = w1;
        }
    }
    __syncthreads();

    // ---- epilogue: mask + 1x1 proj + stats (2 px per thread) ----
    float lsum[8] = {0,0,0,0,0,0,0,0}, lsq[8] = {0,0,0,0,0,0,0,0};
    float lcnt = 0.f;
#pragma unroll
    for (int e = 0; e < 2; e++) {
        const int px = (tid << 1) + e;
        float f[32];
#pragma unroll
        for (int q = 0; q < 16; q++) {
            float2 t2 = *(float2*)&out_sm[px * 34 + (q << 1)];
            f[2 * q] = t2.x; f[2 * q + 1] = t2.y;
        }
        const bool pm = (mskb[px] != 0);
        if (!pm) lcnt += 1.f;
        float* outp = g_cov + bt * (NHEAD * LL) + px;
#pragma unroll
        for (int n = 0; n < 8; n++) {
            float s = 0.f;
            const float4* pv = (const float4*)(prjf + n * 32);
#pragma unroll
            for (int og = 0; og < 8; og++) {
                float4 p4 = pv[og];
                s = fmaf(p4.x, f[og * 4 + 0], s);
                s = fmaf(p4.y, f[og * 4 + 1], s);
                s = fmaf(p4.z, f[og * 4 + 2], s);
                s = fmaf(p4.w, f[og * 4 + 3], s);
            }
            if (pm) s = 0.f;
            outp[n * LL] = s;
            lsum[n] += s;
            lsq[n]  += s * s;
        }
    }
#pragma unroll
    for (int off = 16; off >= 1; off >>= 1) {
#pragma unroll
        for (int n = 0; n < 8; n++) {
            lsum[n] += __shfl_xor_sync(0xffffffffu, lsum[n], off);
            lsq[n]  += __shfl_xor_sync(0xffffffffu, lsq[n],  off);
        }
        lcnt += __shfl_xor_sync(0xffffffffu, lcnt, off);
    }
    if (lane == 0) {
        float* rr = redf + wid * 17;
#pragma unroll
        for (int n = 0; n < 8; n++) { rr[n] = lsum[n]; rr[8 + n] = lsq[n]; }
        rr[16] = lcnt;
    }
    __syncthreads();
    if (tid < 17) {
        float s = 0.f;
#pragma unroll
        for (int w = 0; w < 8; w++) s += redf[w * 17 + tid];
        atomicAdd(&g_stats[tid], s);
    }
}

// ======================================================================
// Kernel 5: masked batch-norm + transpose to [b*n][t][l] output layout
// ======================================================================
__global__ __launch_bounds__(256) void final_kernel(
    const float* __restrict__ gamma, const float* __restrict__ beta,
    float* __restrict__ out)
{
    int vid = blockIdx.x * 256 + threadIdx.x;   // float4 id
    int f = vid << 2;
    int b  = f >> 20;
    int nh = (f >> 17) & 7;
    int t  = (f >> 9) & 255;
    int l  = f & 511;

    float cnt  = g_stats[16];
    float mean = g_stats[nh] / cnt;
    float var  = g_stats[8 + nh] / cnt - mean * mean;
    float sc = rsqrtf(var + EPSV) * __ldg(gamma + nh);
    float sh = __ldg(beta + nh) - mean * sc;

    float4 v = *(const float4*)(g_cov + ((((b << 8) + t) * 8 + nh) << 9) + l);
    const unsigned char* mp = g_mask + (b << 9) + l;
    float4 r;
    r.x = mp[0] ? 0.f : fmaf(v.x, sc, sh);
    r.y = mp[1] ? 0.f : fmaf(v.y, sc, sh);
    r.z = mp[2] ? 0.f : fmaf(v.z, sc, sh);
    r.w = mp[3] ? 0.f : fmaf(v.w, sc, sh);
    ((float4*)out)[vid] = r;
}

// ======================================================================
// Launch
// ======================================================================
extern "C" void kernel_launch(void* const* d_in, const int* in_sizes, int n_in,
                              void* d_out, int out_size)
{
    (void)in_sizes; (void)out_size;
    const bool has_scalars = (n_in >= 14);
    const float*         prev  = (const float*)d_in[0];
    const unsigned char* mask  = (const unsigned char*)d_in[1];
    const float*         curr  = (const float*)d_in[has_scalars ? 3 : 2];
    const int            base  = has_scalars ? 5 : 3;
    const float*         convw = (const float*)d_in[base + 0];
    const float*         convb = (const float*)d_in[base + 1];
    const float*         projw = (const float*)d_in[base + 2];
    const float*         gw1   = (const float*)d_in[base + 3];
    const float*         gb1   = (const float*)d_in[base + 4];
    const float*         gw2   = (const float*)d_in[base + 5];
    const float*         gb2   = (const float*)d_in[base + 6];
    const float*         gamma = (const float*)d_in[base + 7];
    const float*         beta  = (const float*)d_in[base + 8];

    cudaFuncSetAttribute(conv_mma_kernel,
                         cudaFuncAttributeMaxDynamicSharedMemorySize,
                         CONV_SMEM_TOTAL);

    mask_prep_kernel<<<1, 1024>>>(mask);
    weights_prep_kernel<<<13, 256>>>(convw);
    gate_kernel<<<BTN, 128>>>(prev, curr, gw1, gb1, gw2, gb2);
    cumsum_kernel<<<BB * CCH * 2, 256>>>(prev, curr);
    init_stats_kernel<<<1, 32>>>();
    conv_mma_kernel<<<BTN, 256, CONV_SMEM_TOTAL>>>(convb, projw);
    final_kernel<<<8192, 256>>>(gamma, beta, (float*)d_out);
}